// round 4
// baseline (speedup 1.0000x reference)
#include <cuda_runtime.h>

// Problem constants (fixed by reference setup_inputs)
#define B_  4
#define C_  3
#define H_  384
#define W_  1248
#define W4_ (W_/4)                    // 312 chunks of 4 floats per row
#define PLANE_ (H_*W_)                // 479232
#define IN_PER_SIDE_ (B_*C_*H_*W_)    // 5,750,784
#define OUT_PER_SIDE_ ((long long)B_*9*C_*H_*W_)  // 51,757,056
#define THREADS_PER_SIDE_ (B_*C_*H_*W4_)          // 1,437,696

// out[b, (dy*3+dx)*C + c, y, x] = in[b, c, y+dy-1, x+dx-1]  (0 when OOB)
__global__ void __launch_bounds__(256) unfold_kernel(
    const float* __restrict__ left,
    const float* __restrict__ right,
    float* __restrict__ out)
{
    int t = blockIdx.x * blockDim.x + threadIdx.x;
    const int per_side = THREADS_PER_SIDE_;
    if (t >= 2 * per_side) return;

    const float* in = left;
    float* o = out;
    if (t >= per_side) { t -= per_side; in = right; o = out + OUT_PER_SIDE_; }

    int chunk = t % W4_;
    int rem   = t / W4_;
    int y     = rem % H_;
    rem      /= H_;
    int c     = rem % C_;
    int b     = rem / C_;
    int x     = chunk * 4;

    const float* base = in + ((b * C_ + c) * H_) * (long long)W_;

    // v[dy][0..5] = input[y+dy-1][x-1 .. x+4] with zero padding
    float v[3][6];
#pragma unroll
    for (int dy = 0; dy < 3; dy++) {
        int yy = y + dy - 1;
        if (yy < 0 || yy >= H_) {
            v[dy][0] = v[dy][1] = v[dy][2] = v[dy][3] = v[dy][4] = v[dy][5] = 0.f;
        } else {
            const float* row = base + yy * W_ + x;
            float4 cen = *(const float4*)row;          // 16B-aligned (x,W multiples of 4)
            v[dy][1] = cen.x; v[dy][2] = cen.y; v[dy][3] = cen.z; v[dy][4] = cen.w;
            v[dy][0] = (x > 0)        ? __ldg(row - 1) : 0.f;
            v[dy][5] = (x + 4 < W_)   ? __ldg(row + 4) : 0.f;
        }
    }

    // Output base for k=0 (channel index k*C + c)
    float* ob = o + ((((long long)b * 9 * C_ + c) * H_ + y) * W_ + x);

#pragma unroll
    for (int dy = 0; dy < 3; dy++) {
#pragma unroll
        for (int dx = 0; dx < 3; dx++) {
            float4 w;
            w.x = v[dy][dx + 0];
            w.y = v[dy][dx + 1];
            w.z = v[dy][dx + 2];
            w.w = v[dy][dx + 3];
            *(float4*)(ob + (long long)(dy * 3 + dx) * (C_ * PLANE_)) = w;
        }
    }
}

// one_hot = eye(9).reshape(9,1,1,3,3) -> flat idx k*9+m is 1 iff m==k -> idx % 10 == 0
__global__ void onehot_kernel(float* __restrict__ o)
{
    int i = threadIdx.x;
    if (i < 81) o[i] = (i % 10 == 0) ? 1.0f : 0.0f;
}

extern "C" void kernel_launch(void* const* d_in, const int* in_sizes, int n_in,
                              void* d_out, int out_size)
{
    const float* left  = (const float*)d_in[0];
    const float* right = (const float*)d_in[1];
    float* out = (float*)d_out;

    int total_threads = 2 * THREADS_PER_SIDE_;
    int block = 256;
    int grid = (total_threads + block - 1) / block;
    unfold_kernel<<<grid, block>>>(left, right, out);
    onehot_kernel<<<1, 96>>>(out + 2 * OUT_PER_SIDE_);
}

// round 5
// speedup vs baseline: 1.0052x; 1.0052x over previous
#include <cuda_runtime.h>

// Problem constants (fixed by reference setup_inputs)
#define B_  4
#define C_  3
#define H_  384
#define W_  1248
#define W4_ (W_/4)                    // 312 chunks of 4 floats per row
#define PLANE_ (H_*W_)                // 479232
#define IN_PER_SIDE_ (B_*C_*H_*W_)    // 5,750,784
#define OUT_PER_SIDE_ ((long long)B_*9*C_*H_*W_)  // 51,757,056
#define THREADS_PER_SIDE_ (B_*C_*H_*W4_)          // 1,437,696

// out[b, (dy*3+dx)*C + c, y, x] = in[b, c, y+dy-1, x+dx-1]  (0 when OOB)
__global__ void __launch_bounds__(256) unfold_kernel(
    const float* __restrict__ left,
    const float* __restrict__ right,
    float* __restrict__ out)
{
    int t = blockIdx.x * blockDim.x + threadIdx.x;
    const int per_side = THREADS_PER_SIDE_;
    if (t >= 2 * per_side) return;

    const float* in = left;
    float* o = out;
    if (t >= per_side) { t -= per_side; in = right; o = out + OUT_PER_SIDE_; }

    int chunk = t % W4_;
    int rem   = t / W4_;
    int y     = rem % H_;
    rem      /= H_;
    int c     = rem % C_;
    int b     = rem / C_;
    int x     = chunk * 4;

    const float* base = in + ((b * C_ + c) * H_) * (long long)W_;

    // v[dy][0..5] = input[y+dy-1][x-1 .. x+4] with zero padding
    float v[3][6];
#pragma unroll
    for (int dy = 0; dy < 3; dy++) {
        int yy = y + dy - 1;
        if (yy < 0 || yy >= H_) {
            v[dy][0] = v[dy][1] = v[dy][2] = v[dy][3] = v[dy][4] = v[dy][5] = 0.f;
        } else {
            const float* row = base + yy * W_ + x;
            float4 cen = *(const float4*)row;          // 16B-aligned (x,W multiples of 4)
            v[dy][1] = cen.x; v[dy][2] = cen.y; v[dy][3] = cen.z; v[dy][4] = cen.w;
            v[dy][0] = (x > 0)        ? __ldg(row - 1) : 0.f;
            v[dy][5] = (x + 4 < W_)   ? __ldg(row + 4) : 0.f;
        }
    }

    // Output base for k=0 (channel index k*C + c)
    float* ob = o + ((((long long)b * 9 * C_ + c) * H_ + y) * W_ + x);

#pragma unroll
    for (int dy = 0; dy < 3; dy++) {
#pragma unroll
        for (int dx = 0; dx < 3; dx++) {
            float4 w;
            w.x = v[dy][dx + 0];
            w.y = v[dy][dx + 1];
            w.z = v[dy][dx + 2];
            w.w = v[dy][dx + 3];
            *(float4*)(ob + (long long)(dy * 3 + dx) * (C_ * PLANE_)) = w;
        }
    }
}

// one_hot = eye(9).reshape(9,1,1,3,3) -> flat idx k*9+m is 1 iff m==k -> idx % 10 == 0
__global__ void onehot_kernel(float* __restrict__ o)
{
    int i = threadIdx.x;
    if (i < 81) o[i] = (i % 10 == 0) ? 1.0f : 0.0f;
}

extern "C" void kernel_launch(void* const* d_in, const int* in_sizes, int n_in,
                              void* d_out, int out_size)
{
    const float* left  = (const float*)d_in[0];
    const float* right = (const float*)d_in[1];
    float* out = (float*)d_out;

    int total_threads = 2 * THREADS_PER_SIDE_;
    int block = 256;
    int grid = (total_threads + block - 1) / block;
    unfold_kernel<<<grid, block>>>(left, right, out);
    onehot_kernel<<<1, 96>>>(out + 2 * OUT_PER_SIDE_);
}

// round 6
// speedup vs baseline: 1.0284x; 1.0231x over previous
#include <cuda_runtime.h>

// Problem constants (fixed by reference setup_inputs)
#define B_  4
#define C_  3
#define H_  384
#define W_  1248
#define W4_ (W_/4)                    // 312 chunks of 4 floats per row
#define PLANE_ (H_*W_)                // 479232
#define OUT_PER_SIDE_ ((long long)B_*9*C_*H_*W_)  // 51,757,056
#define THREADS_PER_SIDE_ (B_*C_*H_*W4_)          // 1,437,696
#define NBLOCKS_ (2*THREADS_PER_SIDE_/256)        // 11232 (exact)

// out[b, (dy*3+dx)*C + c, y, x] = in[b, c, y+dy-1, x+dx-1]  (0 when OOB)
// Last block writes the 81-element one-hot filter (eye(9) -> idx%10==0).
__global__ void __launch_bounds__(256) unfold_kernel(
    const float* __restrict__ left,
    const float* __restrict__ right,
    float* __restrict__ out)
{
    if (blockIdx.x == NBLOCKS_) {
        int i = threadIdx.x;
        if (i < 81) out[2 * OUT_PER_SIDE_ + i] = (i % 10 == 0) ? 1.0f : 0.0f;
        return;
    }

    int t = blockIdx.x * blockDim.x + threadIdx.x;   // exact fit: NBLOCKS_*256 == 2*per_side

    const float* in = left;
    float* o = out;
    if (t >= THREADS_PER_SIDE_) { t -= THREADS_PER_SIDE_; in = right; o = out + OUT_PER_SIDE_; }

    int chunk = t % W4_;
    int rem   = t / W4_;
    int y     = rem % H_;
    rem      /= H_;
    int c     = rem % C_;
    int b     = rem / C_;
    int x     = chunk * 4;

    const float* base = in + ((b * C_ + c) * H_) * (long long)W_;

    // v[dy][0..5] = input[y+dy-1][x-1 .. x+4] with zero padding
    float v[3][6];
#pragma unroll
    for (int dy = 0; dy < 3; dy++) {
        int yy = y + dy - 1;
        if (yy < 0 || yy >= H_) {
            v[dy][0] = v[dy][1] = v[dy][2] = v[dy][3] = v[dy][4] = v[dy][5] = 0.f;
        } else {
            const float* row = base + yy * W_ + x;
            float4 cen = *(const float4*)row;          // 16B-aligned (x,W multiples of 4)
            v[dy][1] = cen.x; v[dy][2] = cen.y; v[dy][3] = cen.z; v[dy][4] = cen.w;
            v[dy][0] = (x > 0)        ? __ldg(row - 1) : 0.f;
            v[dy][5] = (x + 4 < W_)   ? __ldg(row + 4) : 0.f;
        }
    }

    // Output base for k=0 (channel index k*C + c)
    float* ob = o + ((((long long)b * 9 * C_ + c) * H_ + y) * W_ + x);

#pragma unroll
    for (int dy = 0; dy < 3; dy++) {
#pragma unroll
        for (int dx = 0; dx < 3; dx++) {
            float4 w;
            w.x = v[dy][dx + 0];
            w.y = v[dy][dx + 1];
            w.z = v[dy][dx + 2];
            w.w = v[dy][dx + 3];
            // streaming store: output is never re-read -> evict-first, keep L2 for inputs
            __stcs((float4*)(ob + (long long)(dy * 3 + dx) * (C_ * PLANE_)), w);
        }
    }
}

extern "C" void kernel_launch(void* const* d_in, const int* in_sizes, int n_in,
                              void* d_out, int out_size)
{
    const float* left  = (const float*)d_in[0];
    const float* right = (const float*)d_in[1];
    float* out = (float*)d_out;

    unfold_kernel<<<NBLOCKS_ + 1, 256>>>(left, right, out);
}